// round 3
// baseline (speedup 1.0000x reference)
#include <cuda_runtime.h>
#include <cuda_fp16.h>

// Problem constants
#define NB   256    // batch
#define NT   256    // initial seq len
#define NI   64     // input dim
#define NH   512    // hidden
#define NG   1536   // 3*NH
#define HZ   8      // horizon
#define TMAX 264    // NT + HZ

// Persistent-kernel tiling
#define NCTA  128   // grid size (<=148, single wave)
#define WSTR  536   // smem row stride in halves (1072B = 67*16, word stride 268 % 32 == 12 -> conflict-free)
#define HPSTR 100   // hp smem row stride (floats)

#define SMEM_MAIN (96 * WSTR * 2 + 32 * WSTR * 2 + 32 * HPSTR * 4)  // 150016 B

// ---------------- device scratch (no cudaMalloc allowed) ----------------
__device__ __half   g_whh16[NG * NH];             // fp16 w_hh [G][H]
__device__ __half   g_h16[2][NB * NH];            // fp16 hidden, double buffered
__device__ float    g_xp[(size_t)TMAX * NB * NG]; // x-projections [t][b][g]
__device__ unsigned g_bar;                        // grid barrier counter (monotonic)

// ---------------- helpers ----------------
#define MMA16816(d, a, b0_, b1_)                                             \
  asm volatile(                                                              \
      "mma.sync.aligned.m16n8k16.row.col.f32.f16.f16.f32 "                   \
      "{%0,%1,%2,%3}, {%4,%5,%6,%7}, {%8,%9}, {%0,%1,%2,%3};"                \
      : "+f"(d[0]), "+f"(d[1]), "+f"(d[2]), "+f"(d[3])                       \
      : "r"(a[0]), "r"(a[1]), "r"(a[2]), "r"(a[3]), "r"(b0_), "r"(b1_))

__device__ __forceinline__ void cp16(void* sdst, const void* gsrc) {
  unsigned s = (unsigned)__cvta_generic_to_shared(sdst);
  asm volatile("cp.async.cg.shared.global [%0], [%1], 16;" ::"r"(s), "l"(gsrc));
}

// grid barrier: monotonic counter, all NCTA CTAs resident (single wave)
__device__ __forceinline__ void gbar(unsigned target) {
  __syncthreads();
  if (threadIdx.x == 0) {
    __threadfence();
    atomicAdd(&g_bar, 1u);
    while (*(volatile unsigned*)&g_bar < target) {}
    __threadfence();
  }
  __syncthreads();
}

// ---------------- prep: fp16 weights, zero hidden + barrier ----------------
__global__ void __launch_bounds__(256) k_prep(const float* __restrict__ w_hh) {
  size_t idx = (size_t)blockIdx.x * 256 + threadIdx.x;
  if (idx < (size_t)NG * NH) g_whh16[idx] = __float2half(w_hh[idx]);
  if (idx < (size_t)NB * NH) {
    g_h16[0][idx] = __float2half(0.f);
    g_h16[1][idx] = __float2half(0.f);
  }
  if (idx == 0) g_bar = 0u;
}

// ---------------- bulk input projection (tensor cores, fp16 in / fp32 acc) ----------------
// xp[t][b][g] = sum_i x[b][t][i] * w_ih[g][i] + b_ih[g],  for t < NT
// grid (12, 4, 256): g-tile 128, b-tile 64, t. block 128 (2x2 warps, warp tile 32x64).
__global__ void __launch_bounds__(128) k_bulk(const float* __restrict__ x,
                                              const float* __restrict__ w_ih,
                                              const float* __restrict__ b_ih) {
  __shared__ __half sX[64 * 72];
  __shared__ __half sB[128 * 72];
  const int tid = threadIdx.x;
  const int gb = blockIdx.x * 128;
  const int b0 = blockIdx.y * 64;
  const int t  = blockIdx.z;
  const int wid = tid >> 5, lane = tid & 31;
  const int wm = wid >> 1, wn = wid & 1;
  const int g4 = lane >> 2, t4 = lane & 3;

  for (int j = tid; j < 1024; j += 128) {
    int rb = j >> 4, i4 = (j & 15) * 4;
    float4 v = *(const float4*)(x + ((size_t)(b0 + rb) * NT + t) * NI + i4);
    *(__half2*)(sX + rb * 72 + i4)     = __floats2half2_rn(v.x, v.y);
    *(__half2*)(sX + rb * 72 + i4 + 2) = __floats2half2_rn(v.z, v.w);
  }
  for (int j = tid; j < 2048; j += 128) {
    int r = j >> 4, i4 = (j & 15) * 4;
    float4 v = *(const float4*)(w_ih + (size_t)(gb + r) * NI + i4);
    *(__half2*)(sB + r * 72 + i4)     = __floats2half2_rn(v.x, v.y);
    *(__half2*)(sB + r * 72 + i4 + 2) = __floats2half2_rn(v.z, v.w);
  }
  __syncthreads();

  float acc[2][8][4];
#pragma unroll
  for (int mi = 0; mi < 2; mi++)
#pragma unroll
    for (int ni = 0; ni < 8; ni++)
#pragma unroll
      for (int q = 0; q < 4; q++) acc[mi][ni][q] = 0.f;

#pragma unroll
  for (int ks = 0; ks < 64; ks += 16) {
    unsigned a[2][4];
#pragma unroll
    for (int mi = 0; mi < 2; mi++) {
      const __half* ap = sX + (wm * 32 + mi * 16 + g4) * 72 + ks + t4 * 2;
      a[mi][0] = *(const unsigned*)ap;
      a[mi][1] = *(const unsigned*)(ap + 8 * 72);
      a[mi][2] = *(const unsigned*)(ap + 8);
      a[mi][3] = *(const unsigned*)(ap + 8 * 72 + 8);
    }
#pragma unroll
    for (int ni = 0; ni < 8; ni++) {
      const __half* bp = sB + (wn * 64 + ni * 8 + g4) * 72 + ks + t4 * 2;
      unsigned bf0 = *(const unsigned*)bp;
      unsigned bf1 = *(const unsigned*)(bp + 8);
#pragma unroll
      for (int mi = 0; mi < 2; mi++) MMA16816(acc[mi][ni], a[mi], bf0, bf1);
    }
  }

#pragma unroll
  for (int mi = 0; mi < 2; mi++)
#pragma unroll
    for (int ni = 0; ni < 8; ni++) {
      int row = wm * 32 + mi * 16 + g4;
      int colg = wn * 64 + ni * 8 + t4 * 2;
      int g = gb + colg;
      float bi0 = b_ih[g], bi1 = b_ih[g + 1];
      size_t o0 = ((size_t)t * NB + b0 + row) * NG + g;
      float2 v0 = make_float2(acc[mi][ni][0] + bi0, acc[mi][ni][1] + bi1);
      *(float2*)(g_xp + o0) = v0;
      float2 v1 = make_float2(acc[mi][ni][2] + bi0, acc[mi][ni][3] + bi1);
      *(float2*)(g_xp + o0 + (size_t)8 * NG) = v1;
    }
}

// ---------------- persistent main kernel: full recurrence + FC + appended proj ----------------
// grid NCTA=128 (cid -> b-tile 32 x c-tile 32), block 128 (2x2 warps, warp tile m16 x n48).
__global__ void __launch_bounds__(128, 1)
k_main(const float* __restrict__ b_hh, const float* __restrict__ w_ih,
       const float* __restrict__ b_ih, const float* __restrict__ fc_w,
       const float* __restrict__ fc_b, float* __restrict__ out) {
  extern __shared__ char smem[];
  __half* sW   = (__half*)smem;                              // 96 x WSTR halves (stationary w_hh slice)
  __half* sA   = (__half*)(smem + 96 * WSTR * 2);            // 32 x WSTR halves (h tile, full K)
  float*  sHP  = (float*)(smem + 96 * WSTR * 2 + 32 * WSTR * 2);  // 32 x HPSTR
  __half* sPred = sA;    // alias (iproj phase)
  float*  hsm   = sHP;   // alias (FC phase)

  const int tid = threadIdx.x;
  const int cid = blockIdx.x;
  const int b0 = (cid >> 4) * 32;
  const int c0 = (cid & 15) * 32;
  const int wid = tid >> 5, lane = tid & 31;
  const int wm = wid >> 1, wn = wid & 1;
  const int g4 = lane >> 2, t4 = lane & 3;
  const int c = tid & 31, mrow0 = tid >> 5;

  // stationary weight slice: rows r<96 -> gate (r>>5), col c0+(r&31)
  for (int j = tid; j < 96 * 64; j += 128) {
    int r = j >> 6, k8 = (j & 63) * 8;
    int grow = (r >> 5) * NH + c0 + (r & 31);
    *(uint4*)(sW + r * WSTR + k8) = *(const uint4*)(g_whh16 + (size_t)grow * NH + k8);
  }

  const float br  = b_hh[c0 + c];
  const float bz  = b_hh[NH + c0 + c];
  const float bn_ = b_hh[2 * NH + c0 + c];

  float hreg[8];  // fp32 master h for rows (mrow0 + 4j), col c0+c
#pragma unroll
  for (int j = 0; j < 8; j++) hreg[j] = 0.f;

  __syncthreads();

  unsigned target = 0;
  int par = 0;

  for (int p = 0; p < HZ; p++) {
    const int Tlen = NT + p;
    for (int t = 0; t < Tlen; t++) {
      const __half* hA = g_h16[par];

      // A (h tile) via cp.async, two K-halves for load/compute overlap
      for (int j = tid; j < 1024; j += 128) {
        int r = j >> 5, k8 = (j & 31) * 8;
        cp16(sA + r * WSTR + k8, hA + (size_t)(b0 + r) * NH + k8);
      }
      asm volatile("cp.async.commit_group;");
      for (int j = tid; j < 1024; j += 128) {
        int r = j >> 5, k8 = (j & 31) * 8 + 256;
        cp16(sA + r * WSTR + k8, hA + (size_t)(b0 + r) * NH + k8);
      }
      asm volatile("cp.async.commit_group;");

      // prefetch xp[t] into registers (overlaps mma)
      float xr[8], xz[8], xn[8];
      {
        const float* XP = g_xp + (size_t)t * (NB * NG) + c0 + c;
#pragma unroll
        for (int j = 0; j < 8; j++) {
          size_t base = (size_t)(b0 + mrow0 + 4 * j) * NG;
          xr[j] = XP[base];
          xz[j] = XP[base + NH];
          xn[j] = XP[base + 2 * NH];
        }
      }

      float acc[6][4];
#pragma unroll
      for (int ni = 0; ni < 6; ni++)
#pragma unroll
        for (int q = 0; q < 4; q++) acc[ni][q] = 0.f;

      asm volatile("cp.async.wait_group 1;");
      __syncthreads();

#pragma unroll 4
      for (int ks = 0; ks < 256; ks += 16) {
        unsigned a[4];
        const __half* ap = sA + (wm * 16 + g4) * WSTR + ks + t4 * 2;
        a[0] = *(const unsigned*)ap;
        a[1] = *(const unsigned*)(ap + 8 * WSTR);
        a[2] = *(const unsigned*)(ap + 8);
        a[3] = *(const unsigned*)(ap + 8 * WSTR + 8);
#pragma unroll
        for (int ni = 0; ni < 6; ni++) {
          const __half* bp = sW + (wn * 48 + ni * 8 + g4) * WSTR + ks + t4 * 2;
          unsigned bf0 = *(const unsigned*)bp;
          unsigned bf1 = *(const unsigned*)(bp + 8);
          MMA16816(acc[ni], a, bf0, bf1);
        }
      }

      asm volatile("cp.async.wait_group 0;");
      __syncthreads();

#pragma unroll 4
      for (int ks = 256; ks < 512; ks += 16) {
        unsigned a[4];
        const __half* ap = sA + (wm * 16 + g4) * WSTR + ks + t4 * 2;
        a[0] = *(const unsigned*)ap;
        a[1] = *(const unsigned*)(ap + 8 * WSTR);
        a[2] = *(const unsigned*)(ap + 8);
        a[3] = *(const unsigned*)(ap + 8 * WSTR + 8);
#pragma unroll
        for (int ni = 0; ni < 6; ni++) {
          const __half* bp = sW + (wn * 48 + ni * 8 + g4) * WSTR + ks + t4 * 2;
          unsigned bf0 = *(const unsigned*)bp;
          unsigned bf1 = *(const unsigned*)(bp + 8);
          MMA16816(acc[ni], a, bf0, bf1);
        }
      }

      // acc -> sHP (route r/z/n of same col to one thread)
#pragma unroll
      for (int ni = 0; ni < 6; ni++) {
        int row = wm * 16 + g4;
        int col = wn * 48 + ni * 8 + t4 * 2;
        sHP[row * HPSTR + col]           = acc[ni][0];
        sHP[row * HPSTR + col + 1]       = acc[ni][1];
        sHP[(row + 8) * HPSTR + col]     = acc[ni][2];
        sHP[(row + 8) * HPSTR + col + 1] = acc[ni][3];
      }
      __syncthreads();

      // gates
      __half* hOut = g_h16[par ^ 1];
#pragma unroll
      for (int j = 0; j < 8; j++) {
        int m = mrow0 + 4 * j;
        float hr = sHP[m * HPSTR + c] + br;
        float hz = sHP[m * HPSTR + 32 + c] + bz;
        float hn = sHP[m * HPSTR + 64 + c] + bn_;
        float r = 1.f / (1.f + __expf(-(xr[j] + hr)));
        float z = 1.f / (1.f + __expf(-(xz[j] + hz)));
        float pre = xn[j] + r * hn;
        float n = 2.f / (1.f + __expf(-2.f * pre)) - 1.f;
        float hnew = (1.f - z) * n + z * hreg[j];
        hreg[j] = hnew;
        hOut[(size_t)(b0 + m) * NH + c0 + c] = __float2half(hnew);
      }
      par ^= 1;
      target += NCTA;
      gbar(target);
    }

    // -------- FC head: out[b][p][i] = h @ fc_w^T + fc_b ; rows 2*cid, 2*cid+1 --------
    {
      const __half* hp = g_h16[par];
      for (int j = tid; j < 512; j += 128) {
        int row = j >> 8, k2 = (j & 255) * 2;
        unsigned v = __ldcg((const unsigned*)(hp + (size_t)(2 * cid + row) * NH + k2));
        __half2 h2 = *(__half2*)&v;
        float2 f = __half22float2(h2);
        hsm[row * 512 + k2]     = f.x;
        hsm[row * 512 + k2 + 1] = f.y;
      }
      __syncthreads();
      int i = tid & 63, row = tid >> 6;
      int b = 2 * cid + row;
      const float4* wr = (const float4*)(fc_w + (size_t)i * NH);
      const float* hrow = hsm + row * 512;
      float a0 = 0.f, a1 = 0.f, a2 = 0.f, a3 = 0.f;
#pragma unroll 8
      for (int k4 = 0; k4 < 128; k4++) {
        float4 w = wr[k4];
        a0 += w.x * hrow[k4 * 4];
        a1 += w.y * hrow[k4 * 4 + 1];
        a2 += w.z * hrow[k4 * 4 + 2];
        a3 += w.w * hrow[k4 * 4 + 3];
      }
      out[(size_t)b * (HZ * NI) + p * NI + i] = fc_b[i] + ((a0 + a1) + (a2 + a3));
    }
    target += NCTA;
    gbar(target);

    // -------- appended projection: xp[NT+p][b][g] from the step just predicted --------
    if (p < HZ - 1) {
      for (int j = tid; j < NB * NI; j += 128) {
        int b = j >> 6, i = j & 63;
        float v = __ldcg(out + (size_t)b * (HZ * NI) + p * NI + i);
        sPred[j] = __float2half(v);
      }
      __syncthreads();
      const int g0i = cid * 12;
      const size_t xbase = (size_t)(NT + p) * (NB * NG);
#pragma unroll
      for (int jj = 0; jj < 24; jj++) {
        int idx = tid + 128 * jj;
        int b = idx & 255, gi = idx >> 8;
        int g = g0i + gi;
        const __half2* pr = (const __half2*)(sPred + b * 64);
        const float* wrow = w_ih + (size_t)g * NI;
        float acc2 = b_ih[g];
#pragma unroll
        for (int i2 = 0; i2 < 32; i2++) {
          float2 pv = __half22float2(pr[i2]);
          acc2 += pv.x * wrow[2 * i2] + pv.y * wrow[2 * i2 + 1];
        }
        g_xp[xbase + (size_t)b * NG + g] = acc2;
      }
      __syncthreads();  // sPred (=sA) must be free before next pass's cp.async
    }
  }
}

// ---------------- launch ----------------
extern "C" void kernel_launch(void* const* d_in, const int* in_sizes, int n_in,
                              void* d_out, int out_size) {
  const float* x    = (const float*)d_in[0];
  const float* w_ih = (const float*)d_in[1];
  const float* w_hh = (const float*)d_in[2];
  const float* b_ih = (const float*)d_in[3];
  const float* b_hh = (const float*)d_in[4];
  const float* fc_w = (const float*)d_in[5];
  const float* fc_b = (const float*)d_in[6];
  float* out = (float*)d_out;

  cudaFuncSetAttribute(k_main, cudaFuncAttributeMaxDynamicSharedMemorySize, SMEM_MAIN);

  k_prep<<<3072, 256>>>(w_hh);
  k_bulk<<<dim3(12, 4, 256), 128>>>(x, w_ih, b_ih);
  k_main<<<NCTA, 128, SMEM_MAIN>>>(b_hh, w_ih, b_ih, fc_w, fc_b, out);
}

// round 6
// speedup vs baseline: 1.0227x; 1.0227x over previous
#include <cuda_runtime.h>
#include <cuda_fp16.h>

// Problem constants
#define NB   256    // batch
#define NT   256    // initial seq len
#define NI   64     // input dim
#define NH   512    // hidden
#define NG   1536   // 3*NH
#define HZ   8      // horizon
#define TMAX 264    // NT + HZ

// Persistent-kernel tiling (identical to the passing R3 kernel)
#define NCTA  128   // grid size (<=148, single wave)
#define WSTR  536   // smem row stride in halves (word stride 268 % 32 == 12 -> conflict-free)
#define HPSTR 100   // hp smem row stride (floats)

#define SMEM_MAIN (96 * WSTR * 2 + 32 * WSTR * 2 + 32 * HPSTR * 4)  // 150016 B

// ---------------- device scratch ----------------
__device__ __half   g_whh16[NG * NH];             // fp16 w_hh [G][H]
__device__ __half   g_h16[2][NB * NH];            // fp16 hidden, double buffered
__device__ float    g_xp[(size_t)TMAX * NB * NG]; // x-projections [t][b][g]
__device__ unsigned g_bar;                        // grid barrier counter (monotonic)

// ---------------- helpers ----------------
#define MMA16816(d, a, b0_, b1_)                                             \
  asm volatile(                                                              \
      "mma.sync.aligned.m16n8k16.row.col.f32.f16.f16.f32 "                   \
      "{%0,%1,%2,%3}, {%4,%5,%6,%7}, {%8,%9}, {%0,%1,%2,%3};"                \
      : "+f"(d[0]), "+f"(d[1]), "+f"(d[2]), "+f"(d[3])                       \
      : "r"(a[0]), "r"(a[1]), "r"(a[2]), "r"(a[3]), "r"(b0_), "r"(b1_))

__device__ __forceinline__ void cp16(void* sdst, const void* gsrc) {
  unsigned s = (unsigned)__cvta_generic_to_shared(sdst);
  asm volatile("cp.async.cg.shared.global [%0], [%1], 16;" ::"r"(s), "l"(gsrc));
}

__device__ __forceinline__ void ldsm4(unsigned* r, const void* p) {
  unsigned a = (unsigned)__cvta_generic_to_shared(p);
  asm volatile("ldmatrix.sync.aligned.m8n8.x4.shared.b16 {%0,%1,%2,%3}, [%4];"
               : "=r"(r[0]), "=r"(r[1]), "=r"(r[2]), "=r"(r[3]) : "r"(a));
}

// grid barrier: monotonic counter, all NCTA CTAs resident (single wave) — R3 exact
__device__ __forceinline__ void gbar(unsigned target) {
  __syncthreads();
  if (threadIdx.x == 0) {
    __threadfence();
    atomicAdd(&g_bar, 1u);
    while (*(volatile unsigned*)&g_bar < target) {}
    __threadfence();
  }
  __syncthreads();
}

// ---------------- prep ----------------
__global__ void __launch_bounds__(256) k_prep(const float* __restrict__ w_hh) {
  size_t idx = (size_t)blockIdx.x * 256 + threadIdx.x;
  if (idx < (size_t)NG * NH) g_whh16[idx] = __float2half(w_hh[idx]);
  if (idx < (size_t)NB * NH) {
    g_h16[0][idx] = __float2half(0.f);
    g_h16[1][idx] = __float2half(0.f);
  }
  if (idx == 0) g_bar = 0u;
}

// ---------------- bulk input projection (tensor cores, fp16 in / fp32 acc) ----------------
__global__ void __launch_bounds__(128) k_bulk(const float* __restrict__ x,
                                              const float* __restrict__ w_ih,
                                              const float* __restrict__ b_ih) {
  __shared__ __half sX[64 * 72];
  __shared__ __half sB[128 * 72];
  const int tid = threadIdx.x;
  const int gb = blockIdx.x * 128;
  const int b0 = blockIdx.y * 64;
  const int t  = blockIdx.z;
  const int wid = tid >> 5, lane = tid & 31;
  const int wm = wid >> 1, wn = wid & 1;
  const int g4 = lane >> 2, t4 = lane & 3;

  for (int j = tid; j < 1024; j += 128) {
    int rb = j >> 4, i4 = (j & 15) * 4;
    float4 v = *(const float4*)(x + ((size_t)(b0 + rb) * NT + t) * NI + i4);
    *(__half2*)(sX + rb * 72 + i4)     = __floats2half2_rn(v.x, v.y);
    *(__half2*)(sX + rb * 72 + i4 + 2) = __floats2half2_rn(v.z, v.w);
  }
  for (int j = tid; j < 2048; j += 128) {
    int r = j >> 4, i4 = (j & 15) * 4;
    float4 v = *(const float4*)(w_ih + (size_t)(gb + r) * NI + i4);
    *(__half2*)(sB + r * 72 + i4)     = __floats2half2_rn(v.x, v.y);
    *(__half2*)(sB + r * 72 + i4 + 2) = __floats2half2_rn(v.z, v.w);
  }
  __syncthreads();

  float acc[2][8][4];
#pragma unroll
  for (int mi = 0; mi < 2; mi++)
#pragma unroll
    for (int ni = 0; ni < 8; ni++)
#pragma unroll
      for (int q = 0; q < 4; q++) acc[mi][ni][q] = 0.f;

#pragma unroll
  for (int ks = 0; ks < 64; ks += 16) {
    unsigned a[2][4];
#pragma unroll
    for (int mi = 0; mi < 2; mi++) {
      const __half* ap = sX + (wm * 32 + mi * 16 + g4) * 72 + ks + t4 * 2;
      a[mi][0] = *(const unsigned*)ap;
      a[mi][1] = *(const unsigned*)(ap + 8 * 72);
      a[mi][2] = *(const unsigned*)(ap + 8);
      a[mi][3] = *(const unsigned*)(ap + 8 * 72 + 8);
    }
#pragma unroll
    for (int ni = 0; ni < 8; ni++) {
      const __half* bp = sB + (wn * 64 + ni * 8 + g4) * 72 + ks + t4 * 2;
      unsigned bf0 = *(const unsigned*)bp;
      unsigned bf1 = *(const unsigned*)(bp + 8);
#pragma unroll
      for (int mi = 0; mi < 2; mi++) MMA16816(acc[mi][ni], a[mi], bf0, bf1);
    }
  }

#pragma unroll
  for (int mi = 0; mi < 2; mi++)
#pragma unroll
    for (int ni = 0; ni < 8; ni++) {
      int row = wm * 32 + mi * 16 + g4;
      int colg = wn * 64 + ni * 8 + t4 * 2;
      int g = gb + colg;
      float bi0 = b_ih[g], bi1 = b_ih[g + 1];
      size_t o0 = ((size_t)t * NB + b0 + row) * NG + g;
      *(float2*)(g_xp + o0) = make_float2(acc[mi][ni][0] + bi0, acc[mi][ni][1] + bi1);
      *(float2*)(g_xp + o0 + (size_t)8 * NG) =
          make_float2(acc[mi][ni][2] + bi0, acc[mi][ni][3] + bi1);
    }
}

// ---------------- persistent main kernel (R3 structure; ldmatrix slab loads) ----------------
// grid NCTA=128 (cid -> b-tile 32 x c-tile 32), block 128 (2x2 warps, warp tile m16 x n48).
__global__ void __launch_bounds__(128, 1)
k_main(const float* __restrict__ b_hh, const float* __restrict__ w_ih,
       const float* __restrict__ b_ih, const float* __restrict__ fc_w,
       const float* __restrict__ fc_b, float* __restrict__ out) {
  extern __shared__ char smem[];
  __half* sW   = (__half*)smem;                              // 96 x WSTR halves (stationary w_hh slice)
  __half* sA   = (__half*)(smem + 96 * WSTR * 2);            // 32 x WSTR halves (h tile, full K)
  float*  sHP  = (float*)(smem + 96 * WSTR * 2 + 32 * WSTR * 2);  // 32 x HPSTR
  __half* sPred = sA;   // alias (iproj phase)
  float*  hsm   = sHP;  // alias (FC phase)

  const int tid = threadIdx.x;
  const int cid = blockIdx.x;
  const int b0 = (cid >> 4) * 32;
  const int c0 = (cid & 15) * 32;
  const int wid = tid >> 5, lane = tid & 31;
  const int wm = wid >> 1, wn = wid & 1;
  const int g4 = lane >> 2, t4 = lane & 3;
  const int c = tid & 31, mrow0 = tid >> 5;

  // stationary weight slice (R3 exact): row r<96 -> gate (r>>5), col c0+(r&31)
  for (int j = tid; j < 96 * 64; j += 128) {
    int r = j >> 6, k8 = (j & 63) * 8;
    int grow = (r >> 5) * NH + c0 + (r & 31);
    *(uint4*)(sW + r * WSTR + k8) = *(const uint4*)(g_whh16 + (size_t)grow * NH + k8);
  }

  const float br  = b_hh[c0 + c];
  const float bz  = b_hh[NH + c0 + c];
  const float bn_ = b_hh[2 * NH + c0 + c];

  float hreg[8];
#pragma unroll
  for (int j = 0; j < 8; j++) hreg[j] = 0.f;

  // ldmatrix base pointers (same smem layouts as R3):
  // A x4: lanes 0-15 -> rows wm*16+0..15 @ k0..7, lanes 16-31 -> same rows @ k8..15
  //       => av[0..3] = a0..a3 of mma.m16n8k16
  const int alr = lane & 15, alc = lane >> 4;
  const __half* aP = sA + (wm * 16 + alr) * WSTR + alc * 8;
  // B x4 on [n][k] tile: matrices {n0-7,k0-7},{n0-7,k8-15},{n8-15,k0-7},{n8-15,k8-15}
  //       => bb[0],bb[1] = (b0,b1) for n-block 0; bb[2],bb[3] = (b0,b1) for n-block 1
  const int bq = lane >> 3, bj = lane & 7;
  const __half* bP0 = sW + (wn * 48 + (bq >> 1) * 8 + bj) * WSTR + (bq & 1) * 8;
  const __half* bP1 = bP0 + 16 * WSTR;
  const __half* bP2 = bP0 + 32 * WSTR;

  __syncthreads();

  unsigned target = 0;
  int par = 0;

  for (int p = 0; p < HZ; p++) {
    const int Tlen = NT + p;
    for (int t = 0; t < Tlen; t++) {
      const __half* hA = g_h16[par];

      // A (h tile) via cp.async, two K-halves for load/compute overlap (R3 exact)
      for (int j = tid; j < 1024; j += 128) {
        int r = j >> 5, k8 = (j & 31) * 8;
        cp16(sA + r * WSTR + k8, hA + (size_t)(b0 + r) * NH + k8);
      }
      asm volatile("cp.async.commit_group;");
      for (int j = tid; j < 1024; j += 128) {
        int r = j >> 5, k8 = (j & 31) * 8 + 256;
        cp16(sA + r * WSTR + k8, hA + (size_t)(b0 + r) * NH + k8);
      }
      asm volatile("cp.async.commit_group;");

      // prefetch xp[t] into registers (overlaps mma)
      float xr[8], xz[8], xn[8];
      {
        const float* XP = g_xp + (size_t)t * (NB * NG) + c0 + c;
#pragma unroll
        for (int j = 0; j < 8; j++) {
          size_t base = (size_t)(b0 + mrow0 + 4 * j) * NG;
          xr[j] = XP[base];
          xz[j] = XP[base + NH];
          xn[j] = XP[base + 2 * NH];
        }
      }

      float acc[6][4];
#pragma unroll
      for (int ni = 0; ni < 6; ni++)
#pragma unroll
        for (int q = 0; q < 4; q++) acc[ni][q] = 0.f;

      asm volatile("cp.async.wait_group 1;");
      __syncthreads();

#pragma unroll
      for (int s = 0; s < 16; s++) {
        const int ks = s * 16;
        unsigned av[4], bb0[4], bb1[4], bb2[4];
        ldsm4(av, aP + ks);
        ldsm4(bb0, bP0 + ks);
        ldsm4(bb1, bP1 + ks);
        ldsm4(bb2, bP2 + ks);
        MMA16816(acc[0], av, bb0[0], bb0[1]);
        MMA16816(acc[1], av, bb0[2], bb0[3]);
        MMA16816(acc[2], av, bb1[0], bb1[1]);
        MMA16816(acc[3], av, bb1[2], bb1[3]);
        MMA16816(acc[4], av, bb2[0], bb2[1]);
        MMA16816(acc[5], av, bb2[2], bb2[3]);
      }

      asm volatile("cp.async.wait_group 0;");
      __syncthreads();

#pragma unroll
      for (int s = 16; s < 32; s++) {
        const int ks = s * 16;
        unsigned av[4], bb0[4], bb1[4], bb2[4];
        ldsm4(av, aP + ks);
        ldsm4(bb0, bP0 + ks);
        ldsm4(bb1, bP1 + ks);
        ldsm4(bb2, bP2 + ks);
        MMA16816(acc[0], av, bb0[0], bb0[1]);
        MMA16816(acc[1], av, bb0[2], bb0[3]);
        MMA16816(acc[2], av, bb1[0], bb1[1]);
        MMA16816(acc[3], av, bb1[2], bb1[3]);
        MMA16816(acc[4], av, bb2[0], bb2[1]);
        MMA16816(acc[5], av, bb2[2], bb2[3]);
      }

      // acc -> sHP (R3 exact; acc[ni] covers cols wn*48 + ni*8 + 0..7)
#pragma unroll
      for (int ni = 0; ni < 6; ni++) {
        int row = wm * 16 + g4;
        int col = wn * 48 + ni * 8 + t4 * 2;
        sHP[row * HPSTR + col]           = acc[ni][0];
        sHP[row * HPSTR + col + 1]       = acc[ni][1];
        sHP[(row + 8) * HPSTR + col]     = acc[ni][2];
        sHP[(row + 8) * HPSTR + col + 1] = acc[ni][3];
      }
      __syncthreads();

      // gates (R3 exact)
      __half* hOut = g_h16[par ^ 1];
#pragma unroll
      for (int j = 0; j < 8; j++) {
        int m = mrow0 + 4 * j;
        float hr = sHP[m * HPSTR + c] + br;
        float hz = sHP[m * HPSTR + 32 + c] + bz;
        float hn = sHP[m * HPSTR + 64 + c] + bn_;
        float r = 1.f / (1.f + __expf(-(xr[j] + hr)));
        float z = 1.f / (1.f + __expf(-(xz[j] + hz)));
        float pre = xn[j] + r * hn;
        float n = 2.f / (1.f + __expf(-2.f * pre)) - 1.f;
        float hnew = (1.f - z) * n + z * hreg[j];
        hreg[j] = hnew;
        hOut[(size_t)(b0 + m) * NH + c0 + c] = __float2half(hnew);
      }
      par ^= 1;
      target += NCTA;
      gbar(target);
    }

    // -------- FC head (R3 exact) --------
    {
      const __half* hp = g_h16[par];
      for (int j = tid; j < 512; j += 128) {
        int row = j >> 8, k2 = (j & 255) * 2;
        unsigned v = __ldcg((const unsigned*)(hp + (size_t)(2 * cid + row) * NH + k2));
        float2 f = __half22float2(*(__half2*)&v);
        hsm[row * 512 + k2]     = f.x;
        hsm[row * 512 + k2 + 1] = f.y;
      }
      __syncthreads();
      int i = tid & 63, row = tid >> 6;
      int b = 2 * cid + row;
      const float4* wr = (const float4*)(fc_w + (size_t)i * NH);
      const float* hrow = hsm + row * 512;
      float a0 = 0.f, a1 = 0.f, a2 = 0.f, a3 = 0.f;
#pragma unroll 8
      for (int k4 = 0; k4 < 128; k4++) {
        float4 w = wr[k4];
        a0 += w.x * hrow[k4 * 4];
        a1 += w.y * hrow[k4 * 4 + 1];
        a2 += w.z * hrow[k4 * 4 + 2];
        a3 += w.w * hrow[k4 * 4 + 3];
      }
      out[(size_t)b * (HZ * NI) + p * NI + i] = fc_b[i] + ((a0 + a1) + (a2 + a3));
    }
    target += NCTA;
    gbar(target);

    // -------- appended projection (R3 exact) --------
    if (p < HZ - 1) {
      for (int j = tid; j < NB * NI; j += 128) {
        int b = j >> 6, i = j & 63;
        float v = __ldcg(out + (size_t)b * (HZ * NI) + p * NI + i);
        sPred[j] = __float2half(v);
      }
      __syncthreads();
      const int g0i = cid * 12;
      const size_t xbase = (size_t)(NT + p) * (NB * NG);
#pragma unroll
      for (int jj = 0; jj < 24; jj++) {
        int idx = tid + 128 * jj;
        int b = idx & 255, gi = idx >> 8;
        int g = g0i + gi;
        const __half2* pr = (const __half2*)(sPred + b * 64);
        const float* wrow = w_ih + (size_t)g * NI;
        float acc2 = b_ih[g];
#pragma unroll
        for (int i2 = 0; i2 < 32; i2++) {
          float2 pv = __half22float2(pr[i2]);
          acc2 += pv.x * wrow[2 * i2] + pv.y * wrow[2 * i2 + 1];
        }
        g_xp[xbase + (size_t)b * NG + g] = acc2;
      }
      __syncthreads();  // sPred (=sA) must be free before next pass's cp.async
      target += NCTA;
      gbar(target);
    }
  }
}

// ---------------- launch ----------------
extern "C" void kernel_launch(void* const* d_in, const int* in_sizes, int n_in,
                              void* d_out, int out_size) {
  const float* x    = (const float*)d_in[0];
  const float* w_ih = (const float*)d_in[1];
  const float* w_hh = (const float*)d_in[2];
  const float* b_ih = (const float*)d_in[3];
  const float* b_hh = (const float*)d_in[4];
  const float* fc_w = (const float*)d_in[5];
  const float* fc_b = (const float*)d_in[6];
  float* out = (float*)d_out;

  cudaFuncSetAttribute(k_main, cudaFuncAttributeMaxDynamicSharedMemorySize, SMEM_MAIN);

  k_prep<<<3072, 256>>>(w_hh);
  k_bulk<<<dim3(12, 4, 256), 128>>>(x, w_ih, b_ih);
  k_main<<<NCTA, 128, SMEM_MAIN>>>(b_hh, w_ih, b_ih, fc_w, fc_b, out);
}

// round 7
// speedup vs baseline: 1.0371x; 1.0140x over previous
#include <cuda_runtime.h>
#include <cuda_fp16.h>

// Problem constants
#define NB   256    // batch
#define NT   256    // initial seq len
#define NI   64     // input dim
#define NH   512    // hidden
#define NG   1536   // 3*NH
#define HZ   8      // horizon
#define TMAX 264    // NT + HZ

// Persistent-kernel tiling (identical to the passing R6 kernel)
#define NCTA  128   // grid size (<=148, single wave); 8 b-groups x 16 c-groups
#define WSTR  536   // smem row stride in halves (word stride 268 % 32 == 12 -> conflict-free)
#define HPSTR 100   // hp smem row stride (floats)

#define SMEM_MAIN (96 * WSTR * 2 + 32 * WSTR * 2 + 32 * HPSTR * 4)  // 150016 B

// ---------------- device scratch ----------------
__device__ __half   g_whh16[NG * NH];             // fp16 w_hh [G][H]
__device__ __half   g_h16[2][NB * NH];            // fp16 hidden, double buffered
__device__ float    g_xp[(size_t)TMAX * NB * NG]; // x-projections [t][b][g]
__device__ unsigned g_bar;                        // full-grid barrier counter (pass boundaries)
__device__ volatile unsigned g_flag[NCTA * 32];   // per-CTA step flags, 128B apart

// ---------------- helpers ----------------
#define MMA16816(d, a, b0_, b1_)                                             \
  asm volatile(                                                              \
      "mma.sync.aligned.m16n8k16.row.col.f32.f16.f16.f32 "                   \
      "{%0,%1,%2,%3}, {%4,%5,%6,%7}, {%8,%9}, {%0,%1,%2,%3};"                \
      : "+f"(d[0]), "+f"(d[1]), "+f"(d[2]), "+f"(d[3])                       \
      : "r"(a[0]), "r"(a[1]), "r"(a[2]), "r"(a[3]), "r"(b0_), "r"(b1_))

__device__ __forceinline__ void cp16(void* sdst, const void* gsrc) {
  unsigned s = (unsigned)__cvta_generic_to_shared(sdst);
  asm volatile("cp.async.cg.shared.global [%0], [%1], 16;" ::"r"(s), "l"(gsrc));
}

__device__ __forceinline__ void ldsm4(unsigned* r, const void* p) {
  unsigned a = (unsigned)__cvta_generic_to_shared(p);
  asm volatile("ldmatrix.sync.aligned.m8n8.x4.shared.b16 {%0,%1,%2,%3}, [%4];"
               : "=r"(r[0]), "=r"(r[1]), "=r"(r[2]), "=r"(r[3]) : "r"(a));
}

// full-grid barrier (R3/R6 exact; used only at pass boundaries)
__device__ __forceinline__ void gbar(unsigned target) {
  __syncthreads();
  if (threadIdx.x == 0) {
    __threadfence();
    atomicAdd(&g_bar, 1u);
    while (*(volatile unsigned*)&g_bar < target) {}
    __threadfence();
  }
  __syncthreads();
}

// ---------------- prep ----------------
__global__ void __launch_bounds__(256) k_prep(const float* __restrict__ w_hh) {
  size_t idx = (size_t)blockIdx.x * 256 + threadIdx.x;
  if (idx < (size_t)NG * NH) g_whh16[idx] = __float2half(w_hh[idx]);
  if (idx < (size_t)NB * NH) {
    g_h16[0][idx] = __float2half(0.f);
    g_h16[1][idx] = __float2half(0.f);
  }
  if (idx == 0) g_bar = 0u;
  if (idx < NCTA * 32) g_flag[idx] = 0u;
}

// ---------------- bulk input projection (tensor cores, fp16 in / fp32 acc) ----------------
__global__ void __launch_bounds__(128) k_bulk(const float* __restrict__ x,
                                              const float* __restrict__ w_ih,
                                              const float* __restrict__ b_ih) {
  __shared__ __half sX[64 * 72];
  __shared__ __half sB[128 * 72];
  const int tid = threadIdx.x;
  const int gb = blockIdx.x * 128;
  const int b0 = blockIdx.y * 64;
  const int t  = blockIdx.z;
  const int wid = tid >> 5, lane = tid & 31;
  const int wm = wid >> 1, wn = wid & 1;
  const int g4 = lane >> 2, t4 = lane & 3;

  for (int j = tid; j < 1024; j += 128) {
    int rb = j >> 4, i4 = (j & 15) * 4;
    float4 v = *(const float4*)(x + ((size_t)(b0 + rb) * NT + t) * NI + i4);
    *(__half2*)(sX + rb * 72 + i4)     = __floats2half2_rn(v.x, v.y);
    *(__half2*)(sX + rb * 72 + i4 + 2) = __floats2half2_rn(v.z, v.w);
  }
  for (int j = tid; j < 2048; j += 128) {
    int r = j >> 4, i4 = (j & 15) * 4;
    float4 v = *(const float4*)(w_ih + (size_t)(gb + r) * NI + i4);
    *(__half2*)(sB + r * 72 + i4)     = __floats2half2_rn(v.x, v.y);
    *(__half2*)(sB + r * 72 + i4 + 2) = __floats2half2_rn(v.z, v.w);
  }
  __syncthreads();

  float acc[2][8][4];
#pragma unroll
  for (int mi = 0; mi < 2; mi++)
#pragma unroll
    for (int ni = 0; ni < 8; ni++)
#pragma unroll
      for (int q = 0; q < 4; q++) acc[mi][ni][q] = 0.f;

#pragma unroll
  for (int ks = 0; ks < 64; ks += 16) {
    unsigned a[2][4];
#pragma unroll
    for (int mi = 0; mi < 2; mi++) {
      const __half* ap = sX + (wm * 32 + mi * 16 + g4) * 72 + ks + t4 * 2;
      a[mi][0] = *(const unsigned*)ap;
      a[mi][1] = *(const unsigned*)(ap + 8 * 72);
      a[mi][2] = *(const unsigned*)(ap + 8);
      a[mi][3] = *(const unsigned*)(ap + 8 * 72 + 8);
    }
#pragma unroll
    for (int ni = 0; ni < 8; ni++) {
      const __half* bp = sB + (wn * 64 + ni * 8 + g4) * 72 + ks + t4 * 2;
      unsigned bf0 = *(const unsigned*)bp;
      unsigned bf1 = *(const unsigned*)(bp + 8);
#pragma unroll
      for (int mi = 0; mi < 2; mi++) MMA16816(acc[mi][ni], a[mi], bf0, bf1);
    }
  }

#pragma unroll
  for (int mi = 0; mi < 2; mi++)
#pragma unroll
    for (int ni = 0; ni < 8; ni++) {
      int row = wm * 32 + mi * 16 + g4;
      int colg = wn * 64 + ni * 8 + t4 * 2;
      int g = gb + colg;
      float bi0 = b_ih[g], bi1 = b_ih[g + 1];
      size_t o0 = ((size_t)t * NB + b0 + row) * NG + g;
      *(float2*)(g_xp + o0) = make_float2(acc[mi][ni][0] + bi0, acc[mi][ni][1] + bi1);
      *(float2*)(g_xp + o0 + (size_t)8 * NG) =
          make_float2(acc[mi][ni][2] + bi0, acc[mi][ni][3] + bi1);
    }
}

// ---------------- persistent main kernel ----------------
// grid NCTA=128 (cid -> b-tile 32 x c-tile 32), block 128 (2x2 warps, warp tile m16 x n48).
__global__ void __launch_bounds__(128, 1)
k_main(const float* __restrict__ b_hh, const float* __restrict__ w_ih,
       const float* __restrict__ b_ih, const float* __restrict__ fc_w,
       const float* __restrict__ fc_b, float* __restrict__ out) {
  extern __shared__ char smem[];
  __half* sW   = (__half*)smem;                              // 96 x WSTR halves (stationary w_hh slice)
  __half* sA   = (__half*)(smem + 96 * WSTR * 2);            // 32 x WSTR halves (h tile, full K)
  float*  sHP  = (float*)(smem + 96 * WSTR * 2 + 32 * WSTR * 2);  // 32 x HPSTR
  __half* sPred = sA;   // alias (iproj phase)
  float*  hsm   = sHP;  // alias (FC phase)

  const int tid = threadIdx.x;
  const int cid = blockIdx.x;
  const int grp = cid >> 4;          // b-group; group CTAs are cid in [16*grp, 16*grp+16)
  const int b0 = grp * 32;
  const int c0 = (cid & 15) * 32;
  const int wid = tid >> 5, lane = tid & 31;
  const int wm = wid >> 1, wn = wid & 1;
  const int g4 = lane >> 2, t4 = lane & 3;
  const int c = tid & 31, mrow0 = tid >> 5;

  // stationary weight slice (R6 exact): row r<96 -> gate (r>>5), col c0+(r&31)
  for (int j = tid; j < 96 * 64; j += 128) {
    int r = j >> 6, k8 = (j & 63) * 8;
    int grow = (r >> 5) * NH + c0 + (r & 31);
    *(uint4*)(sW + r * WSTR + k8) = *(const uint4*)(g_whh16 + (size_t)grow * NH + k8);
  }

  const float br  = b_hh[c0 + c];
  const float bz  = b_hh[NH + c0 + c];
  const float bn_ = b_hh[2 * NH + c0 + c];

  float hreg[8];
#pragma unroll
  for (int j = 0; j < 8; j++) hreg[j] = 0.f;

  // ldmatrix base pointers (R6 exact)
  const int alr = lane & 15, alc = lane >> 4;
  const __half* aP = sA + (wm * 16 + alr) * WSTR + alc * 8;
  const int bq = lane >> 3, bj = lane & 7;
  const __half* bP0 = sW + (wn * 48 + (bq >> 1) * 8 + bj) * WSTR + (bq & 1) * 8;
  const __half* bP1 = bP0 + 16 * WSTR;
  const __half* bP2 = bP0 + 32 * WSTR;

  // flag pointer this thread polls (one of the 16 group peers)
  const volatile unsigned* myf = &g_flag[(grp * 16 + (tid & 15)) * 32];

  __syncthreads();

  unsigned sidx = 0;     // steps completed (value carried in flags)
  unsigned gtarget = 0;  // full-grid barrier target
  int par = 0;

  for (int p = 0; p < HZ; p++) {
    const int Tlen = NT + p;
    for (int t = 0; t < Tlen; t++) {
      // prefetch xp[t] into registers (read-only; overlaps the flag wait)
      float xr[8], xz[8], xn[8];
      {
        const float* XP = g_xp + (size_t)t * (NB * NG) + c0 + c;
#pragma unroll
        for (int j = 0; j < 8; j++) {
          size_t base = (size_t)(b0 + mrow0 + 4 * j) * NG;
          xr[j] = XP[base];
          xz[j] = XP[base + NH];
          xn[j] = XP[base + 2 * NH];
        }
      }

      // group flag barrier: wait until all 16 group peers completed sidx steps
      if (tid < 16) {
        while (*myf < sidx) {}
        __threadfence();
      }
      __syncthreads();

      const __half* hA = g_h16[par];

      // A (h tile) via cp.async, two K-halves for load/compute overlap (R6 exact)
      for (int j = tid; j < 1024; j += 128) {
        int r = j >> 5, k8 = (j & 31) * 8;
        cp16(sA + r * WSTR + k8, hA + (size_t)(b0 + r) * NH + k8);
      }
      asm volatile("cp.async.commit_group;");
      for (int j = tid; j < 1024; j += 128) {
        int r = j >> 5, k8 = (j & 31) * 8 + 256;
        cp16(sA + r * WSTR + k8, hA + (size_t)(b0 + r) * NH + k8);
      }
      asm volatile("cp.async.commit_group;");

      float acc[6][4];
#pragma unroll
      for (int ni = 0; ni < 6; ni++)
#pragma unroll
        for (int q = 0; q < 4; q++) acc[ni][q] = 0.f;

      asm volatile("cp.async.wait_group 1;");
      __syncthreads();

#pragma unroll
      for (int s = 0; s < 16; s++) {
        const int ks = s * 16;
        unsigned av[4], bb0[4], bb1[4], bb2[4];
        ldsm4(av, aP + ks);
        ldsm4(bb0, bP0 + ks);
        ldsm4(bb1, bP1 + ks);
        ldsm4(bb2, bP2 + ks);
        MMA16816(acc[0], av, bb0[0], bb0[1]);
        MMA16816(acc[1], av, bb0[2], bb0[3]);
        MMA16816(acc[2], av, bb1[0], bb1[1]);
        MMA16816(acc[3], av, bb1[2], bb1[3]);
        MMA16816(acc[4], av, bb2[0], bb2[1]);
        MMA16816(acc[5], av, bb2[2], bb2[3]);
      }

      asm volatile("cp.async.wait_group 0;");
      __syncthreads();

#pragma unroll
      for (int s = 16; s < 32; s++) {
        const int ks = s * 16;
        unsigned av[4], bb0[4], bb1[4], bb2[4];
        ldsm4(av, aP + ks);
        ldsm4(bb0, bP0 + ks);
        ldsm4(bb1, bP1 + ks);
        ldsm4(bb2, bP2 + ks);
        MMA16816(acc[0], av, bb0[0], bb0[1]);
        MMA16816(acc[1], av, bb0[2], bb0[3]);
        MMA16816(acc[2], av, bb1[0], bb1[1]);
        MMA16816(acc[3], av, bb1[2], bb1[3]);
        MMA16816(acc[4], av, bb2[0], bb2[1]);
        MMA16816(acc[5], av, bb2[2], bb2[3]);
      }

      // acc -> sHP (R6 exact)
#pragma unroll
      for (int ni = 0; ni < 6; ni++) {
        int row = wm * 16 + g4;
        int col = wn * 48 + ni * 8 + t4 * 2;
        sHP[row * HPSTR + col]           = acc[ni][0];
        sHP[row * HPSTR + col + 1]       = acc[ni][1];
        sHP[(row + 8) * HPSTR + col]     = acc[ni][2];
        sHP[(row + 8) * HPSTR + col + 1] = acc[ni][3];
      }
      __syncthreads();

      // gates (R6 exact)
      __half* hOut = g_h16[par ^ 1];
#pragma unroll
      for (int j = 0; j < 8; j++) {
        int m = mrow0 + 4 * j;
        float hr = sHP[m * HPSTR + c] + br;
        float hz = sHP[m * HPSTR + 32 + c] + bz;
        float hn = sHP[m * HPSTR + 64 + c] + bn_;
        float r = 1.f / (1.f + __expf(-(xr[j] + hr)));
        float z = 1.f / (1.f + __expf(-(xz[j] + hz)));
        float pre = xn[j] + r * hn;
        float n = 2.f / (1.f + __expf(-2.f * pre)) - 1.f;
        float hnew = (1.f - z) * n + z * hreg[j];
        hreg[j] = hnew;
        hOut[(size_t)(b0 + m) * NH + c0 + c] = __float2half(hnew);
      }
      par ^= 1;

      // arrive: publish step completion on own flag line
      __syncthreads();
      if (tid == 0) {
        __threadfence();
        g_flag[cid * 32] = sidx + 1;
      }
      sidx++;
    }

    // -------- FC head (reads only own group's h rows) --------
    if (tid < 16) {
      while (*myf < sidx) {}
      __threadfence();
    }
    __syncthreads();
    {
      const __half* hp = g_h16[par];
      for (int j = tid; j < 512; j += 128) {
        int row = j >> 8, k2 = (j & 255) * 2;
        unsigned v = __ldcg((const unsigned*)(hp + (size_t)(2 * cid + row) * NH + k2));
        float2 f = __half22float2(*(__half2*)&v);
        hsm[row * 512 + k2]     = f.x;
        hsm[row * 512 + k2 + 1] = f.y;
      }
      __syncthreads();
      int i = tid & 63, row = tid >> 6;
      int b = 2 * cid + row;
      const float4* wr = (const float4*)(fc_w + (size_t)i * NH);
      const float* hrow = hsm + row * 512;
      float a0 = 0.f, a1 = 0.f, a2 = 0.f, a3 = 0.f;
#pragma unroll 8
      for (int k4 = 0; k4 < 128; k4++) {
        float4 w = wr[k4];
        a0 += w.x * hrow[k4 * 4];
        a1 += w.y * hrow[k4 * 4 + 1];
        a2 += w.z * hrow[k4 * 4 + 2];
        a3 += w.w * hrow[k4 * 4 + 3];
      }
      out[(size_t)b * (HZ * NI) + p * NI + i] = fc_b[i] + ((a0 + a1) + (a2 + a3));
    }

    if (p == HZ - 1) break;

    // full barrier: out written by all CTAs before iproj reads it
    gtarget += NCTA;
    gbar(gtarget);

    // -------- appended projection (R6 exact) --------
    {
      for (int j = tid; j < NB * NI; j += 128) {
        int b = j >> 6, i = j & 63;
        float v = __ldcg(out + (size_t)b * (HZ * NI) + p * NI + i);
        sPred[j] = __float2half(v);
      }
      __syncthreads();
      const int g0i = cid * 12;
      const size_t xbase = (size_t)(NT + p) * (NB * NG);
#pragma unroll
      for (int jj = 0; jj < 24; jj++) {
        int idx = tid + 128 * jj;
        int b = idx & 255, gi = idx >> 8;
        int g = g0i + gi;
        const __half2* pr = (const __half2*)(sPred + b * 64);
        const float* wrow = w_ih + (size_t)g * NI;
        float acc2 = b_ih[g];
#pragma unroll
        for (int i2 = 0; i2 < 32; i2++) {
          float2 pv = __half22float2(pr[i2]);
          acc2 += pv.x * wrow[2 * i2] + pv.y * wrow[2 * i2 + 1];
        }
        g_xp[xbase + (size_t)b * NG + g] = acc2;
      }
      __syncthreads();  // sPred (=sA) must be free before next pass's cp.async
    }

    // full barrier: xp slab visible before next pass
    gtarget += NCTA;
    gbar(gtarget);
  }
}

// ---------------- launch ----------------
extern "C" void kernel_launch(void* const* d_in, const int* in_sizes, int n_in,
                              void* d_out, int out_size) {
  const float* x    = (const float*)d_in[0];
  const float* w_ih = (const float*)d_in[1];
  const float* w_hh = (const float*)d_in[2];
  const float* b_ih = (const float*)d_in[3];
  const float* b_hh = (const float*)d_in[4];
  const float* fc_w = (const float*)d_in[5];
  const float* fc_b = (const float*)d_in[6];
  float* out = (float*)d_out;

  cudaFuncSetAttribute(k_main, cudaFuncAttributeMaxDynamicSharedMemorySize, SMEM_MAIN);

  k_prep<<<3072, 256>>>(w_hh);
  k_bulk<<<dim3(12, 4, 256), 128>>>(x, w_ih, b_ih);
  k_main<<<NCTA, 128, SMEM_MAIN>>>(b_hh, w_ih, b_ih, fc_w, fc_b, out);
}

// round 9
// speedup vs baseline: 1.1401x; 1.0993x over previous
#include <cuda_runtime.h>
#include <cuda_fp16.h>

// Problem constants
#define NB   256    // batch
#define NT   256    // initial seq len
#define NI   64     // input dim
#define NH   512    // hidden
#define NG   1536   // 3*NH
#define HZ   8      // horizon
#define TMAX 264    // NT + HZ

// Persistent-kernel tiling
#define NCTA  128   // 8 b-groups x 16 c-groups
#define NTHR  256   // 8 warps: team 0 = warps 0-3 (K[0:256)), team 1 = warps 4-7 (K[256:512))
#define WSTR  536   // smem row stride in halves (word stride 268 % 32 == 12 -> conflict-free)
#define HPSTR 100   // hp smem row stride (floats)

#define SW_OFF   0
#define SA_OFF   (96 * WSTR * 2)                  // 102912
#define SHP0_OFF (SA_OFF + 32 * WSTR * 2)         // 137216
#define SHP1_OFF (SHP0_OFF + 32 * HPSTR * 4)      // 150016
#define SMEM_MAIN (SHP1_OFF + 32 * HPSTR * 4)     // 162816

// ---------------- device scratch ----------------
__device__ __half   g_whh16[NG * NH];             // fp16 w_hh [G][H]
__device__ __half   g_h16[2][NB * NH];            // fp16 hidden, double buffered
__device__ float    g_xp[(size_t)TMAX * NB * NG]; // x-projections [t][b][g]
__device__ unsigned g_bar;                        // full-grid barrier counter (pass boundaries)
__device__ volatile unsigned g_flag[NCTA * 32];   // per-CTA step flags, 128B apart

// ---------------- helpers ----------------
#define MMA16816(d, a, b0_, b1_)                                             \
  asm volatile(                                                              \
      "mma.sync.aligned.m16n8k16.row.col.f32.f16.f16.f32 "                   \
      "{%0,%1,%2,%3}, {%4,%5,%6,%7}, {%8,%9}, {%0,%1,%2,%3};"                \
      : "+f"(d[0]), "+f"(d[1]), "+f"(d[2]), "+f"(d[3])                       \
      : "r"(a[0]), "r"(a[1]), "r"(a[2]), "r"(a[3]), "r"(b0_), "r"(b1_))

__device__ __forceinline__ void cp16(void* sdst, const void* gsrc) {
  unsigned s = (unsigned)__cvta_generic_to_shared(sdst);
  asm volatile("cp.async.cg.shared.global [%0], [%1], 16;" ::"r"(s), "l"(gsrc));
}

__device__ __forceinline__ void ldsm4(unsigned* r, const void* p) {
  unsigned a = (unsigned)__cvta_generic_to_shared(p);
  asm volatile("ldmatrix.sync.aligned.m8n8.x4.shared.b16 {%0,%1,%2,%3}, [%4];"
               : "=r"(r[0]), "=r"(r[1]), "=r"(r[2]), "=r"(r[3]) : "r"(a));
}

__device__ __forceinline__ unsigned ldcv(const unsigned* p) {
  unsigned v;
  asm volatile("ld.global.cv.u32 %0, [%1];" : "=r"(v) : "l"(p));
  return v;
}

// full-grid barrier (pass boundaries only; R7 exact)
__device__ __forceinline__ void gbar(unsigned target) {
  __syncthreads();
  if (threadIdx.x == 0) {
    __threadfence();
    atomicAdd(&g_bar, 1u);
    while (*(volatile unsigned*)&g_bar < target) {}
    __threadfence();
  }
  __syncthreads();
}

// ---------------- prep ----------------
__global__ void __launch_bounds__(256) k_prep(const float* __restrict__ w_hh) {
  size_t idx = (size_t)blockIdx.x * 256 + threadIdx.x;
  if (idx < (size_t)NG * NH) g_whh16[idx] = __float2half(w_hh[idx]);
  if (idx < (size_t)NB * NH) {
    g_h16[0][idx] = __float2half(0.f);
    g_h16[1][idx] = __float2half(0.f);
  }
  if (idx == 0) g_bar = 0u;
  if (idx < NCTA * 32) g_flag[idx] = 0u;
}

// ---------------- bulk input projection (R7 exact) ----------------
__global__ void __launch_bounds__(128) k_bulk(const float* __restrict__ x,
                                              const float* __restrict__ w_ih,
                                              const float* __restrict__ b_ih) {
  __shared__ __half sX[64 * 72];
  __shared__ __half sB[128 * 72];
  const int tid = threadIdx.x;
  const int gb = blockIdx.x * 128;
  const int b0 = blockIdx.y * 64;
  const int t  = blockIdx.z;
  const int wid = tid >> 5, lane = tid & 31;
  const int wm = wid >> 1, wn = wid & 1;
  const int g4 = lane >> 2, t4 = lane & 3;

  for (int j = tid; j < 1024; j += 128) {
    int rb = j >> 4, i4 = (j & 15) * 4;
    float4 v = *(const float4*)(x + ((size_t)(b0 + rb) * NT + t) * NI + i4);
    *(__half2*)(sX + rb * 72 + i4)     = __floats2half2_rn(v.x, v.y);
    *(__half2*)(sX + rb * 72 + i4 + 2) = __floats2half2_rn(v.z, v.w);
  }
  for (int j = tid; j < 2048; j += 128) {
    int r = j >> 4, i4 = (j & 15) * 4;
    float4 v = *(const float4*)(w_ih + (size_t)(gb + r) * NI + i4);
    *(__half2*)(sB + r * 72 + i4)     = __floats2half2_rn(v.x, v.y);
    *(__half2*)(sB + r * 72 + i4 + 2) = __floats2half2_rn(v.z, v.w);
  }
  __syncthreads();

  float acc[2][8][4];
#pragma unroll
  for (int mi = 0; mi < 2; mi++)
#pragma unroll
    for (int ni = 0; ni < 8; ni++)
#pragma unroll
      for (int q = 0; q < 4; q++) acc[mi][ni][q] = 0.f;

#pragma unroll
  for (int ks = 0; ks < 64; ks += 16) {
    unsigned a[2][4];
#pragma unroll
    for (int mi = 0; mi < 2; mi++) {
      const __half* ap = sX + (wm * 32 + mi * 16 + g4) * 72 + ks + t4 * 2;
      a[mi][0] = *(const unsigned*)ap;
      a[mi][1] = *(const unsigned*)(ap + 8 * 72);
      a[mi][2] = *(const unsigned*)(ap + 8);
      a[mi][3] = *(const unsigned*)(ap + 8 * 72 + 8);
    }
#pragma unroll
    for (int ni = 0; ni < 8; ni++) {
      const __half* bp = sB + (wn * 64 + ni * 8 + g4) * 72 + ks + t4 * 2;
      unsigned bf0 = *(const unsigned*)bp;
      unsigned bf1 = *(const unsigned*)(bp + 8);
#pragma unroll
      for (int mi = 0; mi < 2; mi++) MMA16816(acc[mi][ni], a[mi], bf0, bf1);
    }
  }

#pragma unroll
  for (int mi = 0; mi < 2; mi++)
#pragma unroll
    for (int ni = 0; ni < 8; ni++) {
      int row = wm * 32 + mi * 16 + g4;
      int colg = wn * 64 + ni * 8 + t4 * 2;
      int g = gb + colg;
      float bi0 = b_ih[g], bi1 = b_ih[g + 1];
      size_t o0 = ((size_t)t * NB + b0 + row) * NG + g;
      *(float2*)(g_xp + o0) = make_float2(acc[mi][ni][0] + bi0, acc[mi][ni][1] + bi1);
      *(float2*)(g_xp + o0 + (size_t)8 * NG) =
          make_float2(acc[mi][ni][2] + bi0, acc[mi][ni][3] + bi1);
    }
}

// ---------------- persistent main kernel ----------------
// grid NCTA=128 (cid -> b-tile 32 x c-tile 32), block 256 = 2 K-teams x 4 warps.
__global__ void __launch_bounds__(NTHR, 1)
k_main(const float* __restrict__ b_hh, const float* __restrict__ w_ih,
       const float* __restrict__ b_ih, const float* __restrict__ fc_w,
       const float* __restrict__ fc_b, float* __restrict__ out) {
  extern __shared__ char smem[];
  __half* sW   = (__half*)(smem + SW_OFF);    // 96 x WSTR halves (stationary w_hh slice)
  __half* sA   = (__half*)(smem + SA_OFF);    // 32 x WSTR halves (h tile, full K)
  float*  sHP0 = (float*)(smem + SHP0_OFF);   // team-0 partial, 32 x HPSTR
  float*  sHP1 = (float*)(smem + SHP1_OFF);   // team-1 partial, 32 x HPSTR
  __half* sPred = sA;    // alias (iproj phase)
  float*  hsm   = sHP0;  // alias (FC phase)

  const int tid = threadIdx.x;
  const int cid = blockIdx.x;
  const int grp = cid >> 4;
  const int b0 = grp * 32;
  const int c0 = (cid & 15) * 32;
  const int lane = tid & 31;
  const int team = tid >> 7;           // 0 or 1
  const int ttid = tid & 127;          // tid within team
  const int wid4 = (tid >> 5) & 3;     // warp within team
  const int wm = wid4 >> 1, wn = wid4 & 1;
  const int g4 = lane >> 2, t4 = lane & 3;
  const int koff = team * 256;         // K-half offset (halves)
  const int c = tid & 31, mrow0 = (tid >> 5) & 7;  // gates: 8 row-slots x 4 rows

  // stationary weight slice (R7 layout): row r<96 -> gate (r>>5), col c0+(r&31)
  for (int j = tid; j < 96 * 64; j += NTHR) {
    int r = j >> 6, k8 = (j & 63) * 8;
    int grow = (r >> 5) * NH + c0 + (r & 31);
    *(uint4*)(sW + r * WSTR + k8) = *(const uint4*)(g_whh16 + (size_t)grow * NH + k8);
  }

  const float br  = b_hh[c0 + c];
  const float bz  = b_hh[NH + c0 + c];
  const float bn_ = b_hh[2 * NH + c0 + c];

  float hreg[4];  // fp32 master h for rows mrow0 + 8*j, col c0+c
#pragma unroll
  for (int j = 0; j < 4; j++) hreg[j] = 0.f;

  // ldmatrix base pointers (R7 exact mappings, plus team K-offset)
  const int alr = lane & 15, alc = lane >> 4;
  const __half* aP = sA + (wm * 16 + alr) * WSTR + alc * 8 + koff;
  const int bq = lane >> 3, bj = lane & 7;
  const __half* bP0 = sW + (wn * 48 + (bq >> 1) * 8 + bj) * WSTR + (bq & 1) * 8 + koff;
  const __half* bP1 = bP0 + 16 * WSTR;
  const __half* bP2 = bP0 + 32 * WSTR;

  float* sHPt = team ? sHP1 : sHP0;

  const volatile unsigned* myf = &g_flag[(grp * 16 + (tid & 15)) * 32];

  __syncthreads();

  unsigned sidx = 0;
  unsigned gtarget = 0;
  int par = 0;

  for (int p = 0; p < HZ; p++) {
    const int Tlen = NT + p;
    for (int t = 0; t < Tlen; t++) {
      // prefetch xp[t] (overlaps flag wait)
      float xr[4], xz[4], xn[4];
      {
        const float* XP = g_xp + (size_t)t * (NB * NG) + c0 + c;
#pragma unroll
        for (int j = 0; j < 4; j++) {
          size_t base = (size_t)(b0 + mrow0 + 8 * j) * NG;
          xr[j] = XP[base];
          xz[j] = XP[base + NH];
          xn[j] = XP[base + 2 * NH];
        }
      }

      // group flag barrier: wait until all 16 group peers completed sidx steps
      if (tid < 16) {
        while (*myf < sidx) {}
        __threadfence();
      }
      __syncthreads();

      const __half* hA = g_h16[par];

      // each team loads ITS K-half of the h tile (32 rows x 256 halves)
      for (int j = ttid; j < 1024; j += 128) {
        int r = j >> 5, k8 = (j & 31) * 8 + koff;
        cp16(sA + r * WSTR + k8, hA + (size_t)(b0 + r) * NH + k8);
      }
      asm volatile("cp.async.commit_group;");
      asm volatile("cp.async.wait_group 0;");
      // team barrier: whole team's K-half visible before fragment loads
      asm volatile("bar.sync %0, 128;" ::"r"(1 + team) : "memory");

      float acc[6][4];
#pragma unroll
      for (int ni = 0; ni < 6; ni++)
#pragma unroll
        for (int q = 0; q < 4; q++) acc[ni][q] = 0.f;

#pragma unroll
      for (int s = 0; s < 16; s++) {
        const int ks = s * 16;
        unsigned av[4], bb0[4], bb1[4], bb2[4];
        ldsm4(av, aP + ks);
        ldsm4(bb0, bP0 + ks);
        ldsm4(bb1, bP1 + ks);
        ldsm4(bb2, bP2 + ks);
        MMA16816(acc[0], av, bb0[0], bb0[1]);
        MMA16816(acc[1], av, bb0[2], bb0[3]);
        MMA16816(acc[2], av, bb1[0], bb1[1]);
        MMA16816(acc[3], av, bb1[2], bb1[3]);
        MMA16816(acc[4], av, bb2[0], bb2[1]);
        MMA16816(acc[5], av, bb2[2], bb2[3]);
      }

      // partial acc -> team buffer (R7 mapping)
#pragma unroll
      for (int ni = 0; ni < 6; ni++) {
        int row = wm * 16 + g4;
        int col = wn * 48 + ni * 8 + t4 * 2;
        sHPt[row * HPSTR + col]           = acc[ni][0];
        sHPt[row * HPSTR + col + 1]       = acc[ni][1];
        sHPt[(row + 8) * HPSTR + col]     = acc[ni][2];
        sHPt[(row + 8) * HPSTR + col + 1] = acc[ni][3];
      }
      __syncthreads();

      // gates: hp = sHP0 + sHP1 (K-half partials)
      __half* hOut = g_h16[par ^ 1];
#pragma unroll
      for (int j = 0; j < 4; j++) {
        int m = mrow0 + 8 * j;
        float hr = sHP0[m * HPSTR + c]      + sHP1[m * HPSTR + c]      + br;
        float hz = sHP0[m * HPSTR + 32 + c] + sHP1[m * HPSTR + 32 + c] + bz;
        float hn = sHP0[m * HPSTR + 64 + c] + sHP1[m * HPSTR + 64 + c] + bn_;
        float r = 1.f / (1.f + __expf(-(xr[j] + hr)));
        float z = 1.f / (1.f + __expf(-(xz[j] + hz)));
        float pre = xn[j] + r * hn;
        float n = 2.f / (1.f + __expf(-2.f * pre)) - 1.f;
        float hnew = (1.f - z) * n + z * hreg[j];
        hreg[j] = hnew;
        hOut[(size_t)(b0 + m) * NH + c0 + c] = __float2half(hnew);
      }
      par ^= 1;

      // arrive: publish step completion
      __syncthreads();
      if (tid == 0) {
        __threadfence();
        g_flag[cid * 32] = sidx + 1;
      }
      sidx++;
    }

    // -------- FC head (reads only own group's h rows) --------
    if (tid < 16) {
      while (*myf < sidx) {}
      __threadfence();
    }
    __syncthreads();
    {
      const __half* hp = g_h16[par];
      for (int j = tid; j < 512; j += NTHR) {
        int row = j >> 8, k2 = (j & 255) * 2;
        unsigned v = __ldcg((const unsigned*)(hp + (size_t)(2 * cid + row) * NH + k2));
        float2 f = __half22float2(*(__half2*)&v);
        hsm[row * 512 + k2]     = f.x;
        hsm[row * 512 + k2 + 1] = f.y;
      }
      __syncthreads();
      if (tid < 128) {
        int i = tid & 63, row = tid >> 6;
        int b = 2 * cid + row;
        const float4* wr = (const float4*)(fc_w + (size_t)i * NH);
        const float* hrow = hsm + row * 512;
        float a0 = 0.f, a1 = 0.f, a2 = 0.f, a3 = 0.f;
#pragma unroll 8
        for (int k4 = 0; k4 < 128; k4++) {
          float4 w = wr[k4];
          a0 += w.x * hrow[k4 * 4];
          a1 += w.y * hrow[k4 * 4 + 1];
          a2 += w.z * hrow[k4 * 4 + 2];
          a3 += w.w * hrow[k4 * 4 + 3];
        }
        out[(size_t)b * (HZ * NI) + p * NI + i] = fc_b[i] + ((a0 + a1) + (a2 + a3));
      }
    }

    if (p == HZ - 1) break;

    // full barrier: out written by all CTAs before iproj reads it
    gtarget += NCTA;
    gbar(gtarget);

    // -------- appended projection (R7 logic, 256 threads) --------
    {
      for (int j = tid; j < NB * NI; j += NTHR) {
        int b = j >> 6, i = j & 63;
        float v = __ldcg(out + (size_t)b * (HZ * NI) + p * NI + i);
        sPred[j] = __float2half(v);
      }
      __syncthreads();
      const int g0i = cid * 12;
      const size_t xbase = (size_t)(NT + p) * (NB * NG);
#pragma unroll
      for (int jj = 0; jj < 12; jj++) {
        int idx = tid + NTHR * jj;
        int b = idx & 255, gi = idx >> 8;
        int g = g0i + gi;
        const __half2* pr = (const __half2*)(sPred + b * 64);
        const float* wrow = w_ih + (size_t)g * NI;
        float acc2 = b_ih[g];
#pragma unroll
        for (int i2 = 0; i2 < 32; i2++) {
          float2 pv = __half22float2(pr[i2]);
          acc2 += pv.x * wrow[2 * i2] + pv.y * wrow[2 * i2 + 1];
        }
        g_xp[xbase + (size_t)b * NG + g] = acc2;
      }
      __syncthreads();  // sPred (=sA) must be free before next pass's cp.async
    }

    // full barrier: xp slab visible before next pass
    gtarget += NCTA;
    gbar(gtarget);
  }
}

// ---------------- launch ----------------
extern "C" void kernel_launch(void* const* d_in, const int* in_sizes, int n_in,
                              void* d_out, int out_size) {
  const float* x    = (const float*)d_in[0];
  const float* w_ih = (const float*)d_in[1];
  const float* w_hh = (const float*)d_in[2];
  const float* b_ih = (const float*)d_in[3];
  const float* b_hh = (const float*)d_in[4];
  const float* fc_w = (const float*)d_in[5];
  const float* fc_b = (const float*)d_in[6];
  float* out = (float*)d_out;

  cudaFuncSetAttribute(k_main, cudaFuncAttributeMaxDynamicSharedMemorySize, SMEM_MAIN);

  k_prep<<<3072, 256>>>(w_hh);
  k_bulk<<<dim3(12, 4, 256), 128>>>(x, w_ih, b_ih);
  k_main<<<NCTA, NTHR, SMEM_MAIN>>>(b_hh, w_ih, b_ih, fc_w, fc_b, out);
}

// round 11
// speedup vs baseline: 1.1610x; 1.0184x over previous
#include <cuda_runtime.h>
#include <cuda_fp16.h>

// Problem constants
#define NB   256    // batch
#define NT   256    // initial seq len
#define NI   64     // input dim
#define NH   512    // hidden
#define NG   1536   // 3*NH
#define HZ   8      // horizon
#define TMAX 264    // NT + HZ

// Persistent-kernel tiling
#define NCTA  128   // 8 b-groups x 16 c-groups
#define NTHR  512   // 16 warps: 4 K-teams x 4 warps; team q owns K[q*128,(q+1)*128)
#define WSTR  536   // smem row stride in halves (word stride 268 % 32 == 12 -> conflict-free)
#define HPSTR 100   // hp smem row stride (floats)

#define SW_OFF   0
#define SA_OFF   (96 * WSTR * 2)                   // 102912
#define SHP_OFF  (SA_OFF + 32 * WSTR * 2)          // 137216; 4 buffers of 32*HPSTR floats
#define SHP_SZ   (32 * HPSTR * 4)                  // 12800
#define SMEM_MAIN (SHP_OFF + 4 * SHP_SZ)           // 188416

// ---------------- device scratch ----------------
__device__ __half   g_whh16[NG * NH];             // fp16 w_hh [G][H]
__device__ __half   g_h16[2][NB * NH];            // fp16 hidden, double buffered
__device__ float    g_xp[(size_t)TMAX * NB * NG]; // x-projections [t][b][g]
__device__ unsigned g_bar;                        // full-grid barrier counter (pass boundaries)
__device__ volatile unsigned g_flag[NCTA * 32];   // per-CTA step flags, 128B apart

// ---------------- helpers ----------------
#define MMA16816(d, a, b0_, b1_)                                             \
  asm volatile(                                                              \
      "mma.sync.aligned.m16n8k16.row.col.f32.f16.f16.f32 "                   \
      "{%0,%1,%2,%3}, {%4,%5,%6,%7}, {%8,%9}, {%0,%1,%2,%3};"                \
      : "+f"(d[0]), "+f"(d[1]), "+f"(d[2]), "+f"(d[3])                       \
      : "r"(a[0]), "r"(a[1]), "r"(a[2]), "r"(a[3]), "r"(b0_), "r"(b1_))

__device__ __forceinline__ void cp16(void* sdst, const void* gsrc) {
  unsigned s = (unsigned)__cvta_generic_to_shared(sdst);
  asm volatile("cp.async.cg.shared.global [%0], [%1], 16;" ::"r"(s), "l"(gsrc));
}

__device__ __forceinline__ void ldsm4(unsigned* r, const void* p) {
  unsigned a = (unsigned)__cvta_generic_to_shared(p);
  asm volatile("ldmatrix.sync.aligned.m8n8.x4.shared.b16 {%0,%1,%2,%3}, [%4];"
               : "=r"(r[0]), "=r"(r[1]), "=r"(r[2]), "=r"(r[3]) : "r"(a));
}

__device__ __forceinline__ unsigned ldcv(const unsigned* p) {
  unsigned v;
  asm volatile("ld.global.cv.u32 %0, [%1];" : "=r"(v) : "l"(p));
  return v;
}

// full-grid barrier (pass boundaries only; proven)
__device__ __forceinline__ void gbar(unsigned target) {
  __syncthreads();
  if (threadIdx.x == 0) {
    __threadfence();
    atomicAdd(&g_bar, 1u);
    while (*(volatile unsigned*)&g_bar < target) {}
    __threadfence();
  }
  __syncthreads();
}

// ---------------- prep ----------------
__global__ void __launch_bounds__(256) k_prep(const float* __restrict__ w_hh) {
  size_t idx = (size_t)blockIdx.x * 256 + threadIdx.x;
  if (idx < (size_t)NG * NH) g_whh16[idx] = __float2half(w_hh[idx]);
  if (idx < (size_t)NB * NH) {
    g_h16[0][idx] = __float2half(0.f);
    g_h16[1][idx] = __float2half(0.f);
  }
  if (idx == 0) g_bar = 0u;
  if (idx < NCTA * 32) g_flag[idx] = 0u;
}

// ---------------- bulk input projection (R9 exact) ----------------
__global__ void __launch_bounds__(128) k_bulk(const float* __restrict__ x,
                                              const float* __restrict__ w_ih,
                                              const float* __restrict__ b_ih) {
  __shared__ __half sX[64 * 72];
  __shared__ __half sB[128 * 72];
  const int tid = threadIdx.x;
  const int gb = blockIdx.x * 128;
  const int b0 = blockIdx.y * 64;
  const int t  = blockIdx.z;
  const int wid = tid >> 5, lane = tid & 31;
  const int wm = wid >> 1, wn = wid & 1;
  const int g4 = lane >> 2, t4 = lane & 3;

  for (int j = tid; j < 1024; j += 128) {
    int rb = j >> 4, i4 = (j & 15) * 4;
    float4 v = *(const float4*)(x + ((size_t)(b0 + rb) * NT + t) * NI + i4);
    *(__half2*)(sX + rb * 72 + i4)     = __floats2half2_rn(v.x, v.y);
    *(__half2*)(sX + rb * 72 + i4 + 2) = __floats2half2_rn(v.z, v.w);
  }
  for (int j = tid; j < 2048; j += 128) {
    int r = j >> 4, i4 = (j & 15) * 4;
    float4 v = *(const float4*)(w_ih + (size_t)(gb + r) * NI + i4);
    *(__half2*)(sB + r * 72 + i4)     = __floats2half2_rn(v.x, v.y);
    *(__half2*)(sB + r * 72 + i4 + 2) = __floats2half2_rn(v.z, v.w);
  }
  __syncthreads();

  float acc[2][8][4];
#pragma unroll
  for (int mi = 0; mi < 2; mi++)
#pragma unroll
    for (int ni = 0; ni < 8; ni++)
#pragma unroll
      for (int q = 0; q < 4; q++) acc[mi][ni][q] = 0.f;

#pragma unroll
  for (int ks = 0; ks < 64; ks += 16) {
    unsigned a[2][4];
#pragma unroll
    for (int mi = 0; mi < 2; mi++) {
      const __half* ap = sX + (wm * 32 + mi * 16 + g4) * 72 + ks + t4 * 2;
      a[mi][0] = *(const unsigned*)ap;
      a[mi][1] = *(const unsigned*)(ap + 8 * 72);
      a[mi][2] = *(const unsigned*)(ap + 8);
      a[mi][3] = *(const unsigned*)(ap + 8 * 72 + 8);
    }
#pragma unroll
    for (int ni = 0; ni < 8; ni++) {
      const __half* bp = sB + (wn * 64 + ni * 8 + g4) * 72 + ks + t4 * 2;
      unsigned bf0 = *(const unsigned*)bp;
      unsigned bf1 = *(const unsigned*)(bp + 8);
#pragma unroll
      for (int mi = 0; mi < 2; mi++) MMA16816(acc[mi][ni], a[mi], bf0, bf1);
    }
  }

#pragma unroll
  for (int mi = 0; mi < 2; mi++)
#pragma unroll
    for (int ni = 0; ni < 8; ni++) {
      int row = wm * 32 + mi * 16 + g4;
      int colg = wn * 64 + ni * 8 + t4 * 2;
      int g = gb + colg;
      float bi0 = b_ih[g], bi1 = b_ih[g + 1];
      size_t o0 = ((size_t)t * NB + b0 + row) * NG + g;
      *(float2*)(g_xp + o0) = make_float2(acc[mi][ni][0] + bi0, acc[mi][ni][1] + bi1);
      *(float2*)(g_xp + o0 + (size_t)8 * NG) =
          make_float2(acc[mi][ni][2] + bi0, acc[mi][ni][3] + bi1);
    }
}

// ---------------- persistent main kernel ----------------
// grid NCTA=128 (cid -> b-tile 32 x c-tile 32), block 512 = 4 K-teams x 4 warps.
__global__ void __launch_bounds__(NTHR, 1)
k_main(const float* __restrict__ b_hh, const float* __restrict__ w_ih,
       const float* __restrict__ b_ih, const float* __restrict__ fc_w,
       const float* __restrict__ fc_b, float* __restrict__ out) {
  extern __shared__ char smem[];
  __half* sW  = (__half*)(smem + SW_OFF);
  __half* sA  = (__half*)(smem + SA_OFF);
  float*  sHP[4] = {(float*)(smem + SHP_OFF),
                    (float*)(smem + SHP_OFF + SHP_SZ),
                    (float*)(smem + SHP_OFF + 2 * SHP_SZ),
                    (float*)(smem + SHP_OFF + 3 * SHP_SZ)};
  __half* sPred = sA;       // alias (iproj phase)
  float*  hsm   = sHP[0];   // alias (FC phase)

  const int tid = threadIdx.x;
  const int cid = blockIdx.x;
  const int grp = cid >> 4;
  const int b0 = grp * 32;
  const int c0 = (cid & 15) * 32;
  const int lane = tid & 31;
  const int team = tid >> 7;           // 0..3
  const int ttid = tid & 127;          // tid within team
  const int wid4 = (tid >> 5) & 3;     // warp within team
  const int wm = wid4 >> 1, wn = wid4 & 1;
  const int g4 = lane >> 2, t4 = lane & 3;
  const int koff = team * 128;         // K-quarter offset (halves)
  const int c = tid & 31, mrow0 = tid >> 5;  // gates: 16 row-slots x 2 rows

  // stationary weight slice: row r<96 -> gate (r>>5), col c0+(r&31)
  for (int j = tid; j < 96 * 64; j += NTHR) {
    int r = j >> 6, k8 = (j & 63) * 8;
    int grow = (r >> 5) * NH + c0 + (r & 31);
    *(uint4*)(sW + r * WSTR + k8) = *(const uint4*)(g_whh16 + (size_t)grow * NH + k8);
  }

  const float br  = b_hh[c0 + c];
  const float bz  = b_hh[NH + c0 + c];
  const float bn_ = b_hh[2 * NH + c0 + c];

  float hreg[2];  // fp32 master h for rows mrow0 + 16*j, col c0+c
#pragma unroll
  for (int j = 0; j < 2; j++) hreg[j] = 0.f;

  // ldmatrix base pointers (proven mappings, plus team K-offset)
  const int alr = lane & 15, alc = lane >> 4;
  const __half* aP = sA + (wm * 16 + alr) * WSTR + alc * 8 + koff;
  const int bq = lane >> 3, bj = lane & 7;
  const __half* bP0 = sW + (wn * 48 + (bq >> 1) * 8 + bj) * WSTR + (bq & 1) * 8 + koff;
  const __half* bP1 = bP0 + 16 * WSTR;
  const __half* bP2 = bP0 + 32 * WSTR;

  float* sHPt = sHP[team];

  const volatile unsigned* myf = &g_flag[(grp * 16 + (tid & 15)) * 32];

  __syncthreads();

  unsigned sidx = 0;
  unsigned gtarget = 0;
  int par = 0;

  for (int p = 0; p < HZ; p++) {
    const int Tlen = NT + p;
    for (int t = 0; t < Tlen; t++) {
      // prefetch xp[t] (overlaps flag wait)
      float xr[2], xz[2], xn[2];
      {
        const float* XP = g_xp + (size_t)t * (NB * NG) + c0 + c;
#pragma unroll
        for (int j = 0; j < 2; j++) {
          size_t base = (size_t)(b0 + mrow0 + 16 * j) * NG;
          xr[j] = XP[base];
          xz[j] = XP[base + NH];
          xn[j] = XP[base + 2 * NH];
        }
      }

      // group flag barrier (R9 exact): wait until all 16 group peers completed sidx steps
      if (tid < 16) {
        while (*myf < sidx) {}
        __threadfence();
      }
      __syncthreads();

      const __half* hA = g_h16[par];

      // each team loads ITS K-quarter of the h tile (32 rows x 128 halves)
      for (int j = ttid; j < 512; j += 128) {
        int r = j >> 4, k8 = (j & 15) * 8 + koff;
        cp16(sA + r * WSTR + k8, hA + (size_t)(b0 + r) * NH + k8);
      }
      asm volatile("cp.async.commit_group;");
      asm volatile("cp.async.wait_group 0;");
      // team barrier: whole team's K-quarter visible before fragment loads
      asm volatile("bar.sync %0, 128;" ::"r"(1 + team) : "memory");

      float acc[6][4];
#pragma unroll
      for (int ni = 0; ni < 6; ni++)
#pragma unroll
        for (int q = 0; q < 4; q++) acc[ni][q] = 0.f;

#pragma unroll
      for (int s = 0; s < 8; s++) {
        const int ks = s * 16;
        unsigned av[4], bb0[4], bb1[4], bb2[4];
        ldsm4(av, aP + ks);
        ldsm4(bb0, bP0 + ks);
        ldsm4(bb1, bP1 + ks);
        ldsm4(bb2, bP2 + ks);
        MMA16816(acc[0], av, bb0[0], bb0[1]);
        MMA16816(acc[1], av, bb0[2], bb0[3]);
        MMA16816(acc[2], av, bb1[0], bb1[1]);
        MMA16816(acc[3], av, bb1[2], bb1[3]);
        MMA16816(acc[4], av, bb2[0], bb2[1]);
        MMA16816(acc[5], av, bb2[2], bb2[3]);
      }

      // partial acc -> team buffer (proven mapping)
#pragma unroll
      for (int ni = 0; ni < 6; ni++) {
        int row = wm * 16 + g4;
        int col = wn * 48 + ni * 8 + t4 * 2;
        sHPt[row * HPSTR + col]           = acc[ni][0];
        sHPt[row * HPSTR + col + 1]       = acc[ni][1];
        sHPt[(row + 8) * HPSTR + col]     = acc[ni][2];
        sHPt[(row + 8) * HPSTR + col + 1] = acc[ni][3];
      }
      __syncthreads();

      // gates: hp = sum of 4 K-quarter partials
      __half* hOut = g_h16[par ^ 1];
#pragma unroll
      for (int j = 0; j < 2; j++) {
        int m = mrow0 + 16 * j;
        float hr = br, hz = bz, hn = bn_;
#pragma unroll
        for (int q = 0; q < 4; q++) {
          hr += sHP[q][m * HPSTR + c];
          hz += sHP[q][m * HPSTR + 32 + c];
          hn += sHP[q][m * HPSTR + 64 + c];
        }
        float r = 1.f / (1.f + __expf(-(xr[j] + hr)));
        float z = 1.f / (1.f + __expf(-(xz[j] + hz)));
        float pre = xn[j] + r * hn;
        float n = 2.f / (1.f + __expf(-2.f * pre)) - 1.f;
        float hnew = (1.f - z) * n + z * hreg[j];
        hreg[j] = hnew;
        hOut[(size_t)(b0 + m) * NH + c0 + c] = __float2half(hnew);
      }
      par ^= 1;

      // arrive: publish step completion
      __syncthreads();
      if (tid == 0) {
        __threadfence();
        g_flag[cid * 32] = sidx + 1;
      }
      sidx++;
    }

    // -------- FC head (reads only own group's h rows) --------
    if (tid < 16) {
      while (*myf < sidx) {}
      __threadfence();
    }
    __syncthreads();
    {
      const __half* hp = g_h16[par];
      for (int j = tid; j < 512; j += NTHR) {
        int row = j >> 8, k2 = (j & 255) * 2;
        unsigned v = __ldcg((const unsigned*)(hp + (size_t)(2 * cid + row) * NH + k2));
        float2 f = __half22float2(*(__half2*)&v);
        hsm[row * 512 + k2]     = f.x;
        hsm[row * 512 + k2 + 1] = f.y;
      }
      __syncthreads();
      if (tid < 128) {
        int i = tid & 63, row = tid >> 6;
        int b = 2 * cid + row;
        const float4* wr = (const float4*)(fc_w + (size_t)i * NH);
        const float* hrow = hsm + row * 512;
        float a0 = 0.f, a1 = 0.f, a2 = 0.f, a3 = 0.f;
#pragma unroll 8
        for (int k4 = 0; k4 < 128; k4++) {
          float4 w = wr[k4];
          a0 += w.x * hrow[k4 * 4];
          a1 += w.y * hrow[k4 * 4 + 1];
          a2 += w.z * hrow[k4 * 4 + 2];
          a3 += w.w * hrow[k4 * 4 + 3];
        }
        out[(size_t)b * (HZ * NI) + p * NI + i] = fc_b[i] + ((a0 + a1) + (a2 + a3));
      }
    }

    if (p == HZ - 1) break;

    // full barrier: out written by all CTAs before iproj reads it
    gtarget += NCTA;
    gbar(gtarget);

    // -------- appended projection --------
    {
      for (int j = tid; j < NB * NI; j += NTHR) {
        int b = j >> 6, i = j & 63;
        float v = __ldcg(out + (size_t)b * (HZ * NI) + p * NI + i);
        sPred[j] = __float2half(v);
      }
      __syncthreads();
      const int g0i = cid * 12;
      const size_t xbase = (size_t)(NT + p) * (NB * NG);
#pragma unroll
      for (int jj = 0; jj < 6; jj++) {
        int idx = tid + NTHR * jj;
        int b = idx & 255, gi = idx >> 8;
        int g = g0i + gi;
        const __half2* pr = (const __half2*)(sPred + b * 64);
        const float* wrow = w_ih + (size_t)g * NI;
        float acc2 = b_ih[g];
#pragma unroll
        for (int i2 = 0; i2 < 32; i2++) {
          float2 pv = __half22float2(pr[i2]);
          acc2 += pv.x * wrow[2 * i2] + pv.y * wrow[2 * i2 + 1];
        }
        g_xp[xbase + (size_t)b * NG + g] = acc2;
      }
      __syncthreads();  // sPred (=sA) must be free before next pass's cp.async
    }

    // full barrier: xp slab visible before next pass
    gtarget += NCTA;
    gbar(gtarget);
  }
}

// ---------------- launch ----------------
extern "C" void kernel_launch(void* const* d_in, const int* in_sizes, int n_in,
                              void* d_out, int out_size) {
  const float* x    = (const float*)d_in[0];
  const float* w_ih = (const float*)d_in[1];
  const float* w_hh = (const float*)d_in[2];
  const float* b_ih = (const float*)d_in[3];
  const float* b_hh = (const float*)d_in[4];
  const float* fc_w = (const float*)d_in[5];
  const float* fc_b = (const float*)d_in[6];
  float* out = (float*)d_out;

  cudaFuncSetAttribute(k_main, cudaFuncAttributeMaxDynamicSharedMemorySize, SMEM_MAIN);

  k_prep<<<3072, 256>>>(w_hh);
  k_bulk<<<dim3(12, 4, 256), 128>>>(x, w_ih, b_ih);
  k_main<<<NCTA, NTHR, SMEM_MAIN>>>(b_hh, w_ih, b_ih, fc_w, fc_b, out);
}